// round 16
// baseline (speedup 1.0000x reference)
#include <cuda_runtime.h>
#include <cuda_bf16.h>
#include <cstdint>

#define NEG_INF (-1e9f)
#define KDIM 1024
#define NCOLS 256            // 128 q | 128 k (u-head removed from GEMM)
#define XSTR 72              // X smem stride (bf16 units): 64 + 8 pad
#define WSTR 264             // W smem stride (bf16 units): 256 + 8 pad
#define QK_STRIDE 264
#define LG_STRIDE 68
#define U_STRIDE 12
#define CHUNK 64
#define NCHUNK 16
#define THREADS 256
// mainloop: Xs [2][64][72] bf16 @0 (18432B), Ws [2][64][264] bf16 @18432 (67584B) -> 86016
// epilogue (aliased): QK [64][264] bf16 @0 (33792B), U [64][12] f32 @33792 (3072B),
//                     LG [64][68] f32 @36864 (17408B) -> 54272
// bias (dedicated): @86016, 272 floats -> 1088B
#define BIAS_OFF 86016
#define SMEM_BYTES 87104

__device__ __nv_bfloat16 g_W[KDIM * NCOLS];
__device__ int g_tbl[4672];

__constant__ int c_ddr[8] = {1, 1, 0, -1, -1, -1, 0, 1};
__constant__ int c_ddc[8] = {0, 1, 1, 1, 0, -1, -1, -1};
__constant__ int c_kdr[8] = {2, 1, -1, -2, -2, -1, 1, 2};
__constant__ int c_kdc[8] = {1, 2, 2, 1, -1, -2, -2, -1};

__global__ void prep_w(const float* __restrict__ Wq, const float* __restrict__ Wk) {
    int k = blockIdx.x;
    int c = threadIdx.x;      // 0..255
    float v = (c < 128) ? Wq[k * 128 + c] : Wk[k * 128 + (c - 128)];
    g_W[k * NCOLS + c] = __float2bfloat16(v);

    if (c < 5) {
        int e = blockIdx.x * 5 + c;
        if (e < 4672) {
            int f = e / 73, p = e - f * 73;
            int r = f >> 3, cc = f & 7;
            int s = -1;
            if (p < 64) {
                int nr, nc;
                if (p < 56) {
                    int d = p / 7, dist = p - d * 7 + 1;
                    nr = r + c_ddr[d] * dist;
                    nc = cc + c_ddc[d] * dist;
                } else {
                    int i = p - 56;
                    nr = r + c_kdr[i];
                    nc = cc + c_kdc[i];
                }
                if (((unsigned)nr < 8u) && ((unsigned)nc < 8u)) s = f * LG_STRIDE + nr * 8 + nc;
            } else {
                if (r == 6) s = 0x40000000 | (f * U_STRIDE + (p - 64));
            }
            g_tbl[e] = s;
        }
    }
}

// ---------------- device helpers ----------------
__device__ __forceinline__ uint32_t smem_u32(const void* p) {
    return (uint32_t)__cvta_generic_to_shared(p);
}
__device__ __forceinline__ uint32_t pack2(float a, float b) {
    __nv_bfloat162 h = __floats2bfloat162_rn(a, b);
    return *reinterpret_cast<uint32_t*>(&h);
}
__device__ __forceinline__ void ldsm_x4(uint32_t& r0, uint32_t& r1, uint32_t& r2, uint32_t& r3, uint32_t a) {
    asm volatile("ldmatrix.sync.aligned.m8n8.x4.shared.b16 {%0,%1,%2,%3}, [%4];"
                 : "=r"(r0), "=r"(r1), "=r"(r2), "=r"(r3) : "r"(a));
}
__device__ __forceinline__ void ldsm_x4t(uint32_t& r0, uint32_t& r1, uint32_t& r2, uint32_t& r3, uint32_t a) {
    asm volatile("ldmatrix.sync.aligned.m8n8.x4.trans.shared.b16 {%0,%1,%2,%3}, [%4];"
                 : "=r"(r0), "=r"(r1), "=r"(r2), "=r"(r3) : "r"(a));
}
__device__ __forceinline__ void ldsm_x2(uint32_t& r0, uint32_t& r1, uint32_t a) {
    asm volatile("ldmatrix.sync.aligned.m8n8.x2.shared.b16 {%0,%1}, [%2];"
                 : "=r"(r0), "=r"(r1) : "r"(a));
}
__device__ __forceinline__ void mma_bf16(float* d, const uint32_t* a, const uint32_t* b) {
    asm volatile(
        "mma.sync.aligned.m16n8k16.row.col.f32.bf16.bf16.f32 "
        "{%0,%1,%2,%3}, {%4,%5,%6,%7}, {%8,%9}, {%0,%1,%2,%3};"
        : "+f"(d[0]), "+f"(d[1]), "+f"(d[2]), "+f"(d[3])
        : "r"(a[0]), "r"(a[1]), "r"(a[2]), "r"(a[3]), "r"(b[0]), "r"(b[1]));
}
__device__ __forceinline__ void cp_async16(uint32_t dst, const void* src) {
    asm volatile("cp.async.cg.shared.global [%0], [%1], 16;" :: "r"(dst), "l"(src));
}

extern __shared__ char smem[];

__global__ void __launch_bounds__(THREADS, 2)
policy_kernel(const float* __restrict__ x,
              const float* __restrict__ bq, const float* __restrict__ bk,
              const float* __restrict__ Wu, const float* __restrict__ bu,
              float* __restrict__ out) {
    __nv_bfloat16* Xs = (__nv_bfloat16*)smem;            // [2][64][XSTR]
    __nv_bfloat16* Ws = (__nv_bfloat16*)(smem + 18432);  // [2][64][WSTR]
    float* bias_s = (float*)(smem + BIAS_OFF);           // 256 qk | 9 u

    const int t = threadIdx.x;
    const int w = t >> 5, lane = t & 31;
    const int g = lane >> 2, tig = lane & 3;
    const int warp_m = w >> 2, warp_n = w & 3;   // 2x4 warp grid; warp tile 32 x 64

    const float* xbase = x + (size_t)blockIdx.x * 64 * KDIM;  // 1 board

    if (t < 256) bias_s[t] = (t < 128) ? bq[t] : bk[t - 128];
    if (t < 9)   bias_s[256 + t] = bu[t];

    float acc[2][8][4];
    #pragma unroll
    for (int mt = 0; mt < 2; mt++)
        #pragma unroll
        for (int nt = 0; nt < 8; nt++)
            #pragma unroll
            for (int i = 0; i < 4; i++) acc[mt][nt][i] = 0.0f;

    float u_acc = 0.0f;      // warp w: promo row 48+w; lanes 0-8: col

    float4 xr[4];

    // 64 rows x 64 cols per chunk: idx = t + i*256 -> row = idx>>3, c8 = idx&7 (8 floats)
    auto load_x = [&](int k0) {
        #pragma unroll
        for (int i = 0; i < 2; i++) {
            int idx = t + i * THREADS;
            int row = idx >> 3, c8 = idx & 7;
            const float* src = xbase + (size_t)row * KDIM + k0 + c8 * 8;
            xr[2 * i]     = *(const float4*)src;
            xr[2 * i + 1] = *(const float4*)(src + 4);
        }
    };
    auto store_x = [&](int buf) {
        __nv_bfloat16* Xb = Xs + buf * 64 * XSTR;
        #pragma unroll
        for (int i = 0; i < 2; i++) {
            int idx = t + i * THREADS;
            int row = idx >> 3, c8 = idx & 7;
            uint4 p;
            p.x = pack2(xr[2 * i].x,     xr[2 * i].y);
            p.y = pack2(xr[2 * i].z,     xr[2 * i].w);
            p.z = pack2(xr[2 * i + 1].x, xr[2 * i + 1].y);
            p.w = pack2(xr[2 * i + 1].z, xr[2 * i + 1].w);
            *(uint4*)(Xb + row * XSTR + c8 * 8) = p;
        }
    };
    auto load_w = [&](int c, int buf) {
        const __nv_bfloat16* src = g_W + (size_t)c * CHUNK * NCOLS;
        __nv_bfloat16* Wb = Ws + buf * 64 * WSTR;
        #pragma unroll
        for (int i = 0; i < 8; i++) {            // 2048 granules / 256 = 8 exact
            int idx = t + i * THREADS;
            int row = idx >> 5, cc = idx & 31;
            cp_async16(smem_u32(Wb + row * WSTR + cc * 8), src + row * NCOLS + cc * 8);
        }
        asm volatile("cp.async.commit_group;");
    };
    auto compute = [&](int c) {
        const __nv_bfloat16* Xb = Xs + (c & 1) * 64 * XSTR;
        const __nv_bfloat16* Wb = Ws + (c & 1) * 64 * WSTR;
        const int arow = 32 * warp_m;
        #pragma unroll
        for (int ks = 0; ks < 4; ks++) {
            uint32_t afr[2][4];
            #pragma unroll
            for (int mt = 0; mt < 2; mt++) {
                const __nv_bfloat16* ap =
                    Xb + (arow + 16 * mt + (lane & 15)) * XSTR + ks * 16 + (lane >> 4) * 8;
                ldsm_x4(afr[mt][0], afr[mt][1], afr[mt][2], afr[mt][3], smem_u32(ap));
            }
            const __nv_bfloat16* brow = Wb + (ks * 16 + (lane & 15)) * WSTR + 64 * warp_n;
            #pragma unroll
            for (int nb = 0; nb < 4; nb++) {
                uint32_t bfr[4];
                ldsm_x4t(bfr[0], bfr[1], bfr[2], bfr[3],
                         smem_u32(brow + nb * 16 + (lane >> 4) * 8));
                mma_bf16(acc[0][2 * nb],     afr[0], bfr);
                mma_bf16(acc[1][2 * nb],     afr[1], bfr);
                mma_bf16(acc[0][2 * nb + 1], afr[0], bfr + 2);
                mma_bf16(acc[1][2 * nb + 1], afr[1], bfr + 2);
            }
        }
    };
    // u-head on the FMA pipe: warp w owns promo row 48+w, lanes 0-8 own the 9 cols
    auto accum_u = [&](int c) {
        if (lane < 9) {
            const __nv_bfloat16* xrow = Xs + (c & 1) * 64 * XSTR + (48 + w) * XSTR;
            const float* wu = Wu + (size_t)c * CHUNK * 9 + lane;
            #pragma unroll 8
            for (int kk = 0; kk < CHUNK; kk++)
                u_acc += __bfloat162float(xrow[kk]) * __ldg(wu + kk * 9);
        }
    };

    // ---- mainloop: 16 K-chunks, double buffered (R10-proven schedule) ----
    load_x(0);
    load_w(0, 0);
    store_x(0);
    asm volatile("cp.async.wait_group 0;");
    __syncthreads();
    for (int c = 0; c < NCHUNK; c++) {
        int nb = (c + 1) & 1;
        if (c + 1 < NCHUNK) {
            load_x((c + 1) * CHUNK);
            load_w(c + 1, nb);
        }
        compute(c);
        accum_u(c);
        if (c + 1 < NCHUNK) {
            store_x(nb);
            asm volatile("cp.async.wait_group 0;");
        }
        __syncthreads();
    }

    // ---- epilogue: q,k -> smem bf16 (+bias), u -> smem f32 (+bu) ----
    __nv_bfloat16* QK = (__nv_bfloat16*)smem;   // [64][QK_STRIDE]
    float* U  = (float*)(smem + 33792);         // [64][U_STRIDE]
    float* LG = (float*)(smem + 36864);         // [64][LG_STRIDE]

    #pragma unroll
    for (int mt = 0; mt < 2; mt++) {
        int r0 = 32 * warp_m + 16 * mt + g;
        #pragma unroll
        for (int nt = 0; nt < 8; nt++) {
            int c0 = 64 * warp_n + 8 * nt + 2 * tig;
            #pragma unroll
            for (int half = 0; half < 2; half++) {
                int row = r0 + 8 * half;
                *(uint32_t*)(QK + row * QK_STRIDE + c0) =
                    pack2(acc[mt][nt][2 * half + 0] + bias_s[c0],
                          acc[mt][nt][2 * half + 1] + bias_s[c0 + 1]);
            }
        }
    }
    if (lane < 9) U[(48 + w) * U_STRIDE + lane] = u_acc + bias_s[256 + lane];
    __syncthreads();

    // ---- logits = (q @ k^T) * SCALE ----
    {
        const int lm = w & 3, ln = w >> 2;     // 4 m-tiles of 16, 2 n-tiles of 32
        float a2[4][4];
        #pragma unroll
        for (int nt = 0; nt < 4; nt++)
            #pragma unroll
            for (int i = 0; i < 4; i++) a2[nt][i] = 0.0f;

        #pragma unroll
        for (int ks = 0; ks < 8; ks++) {
            uint32_t afr[4];
            const __nv_bfloat16* ap =
                QK + (16 * lm + (lane & 15)) * QK_STRIDE + ks * 16 + (lane >> 4) * 8;
            ldsm_x4(afr[0], afr[1], afr[2], afr[3], smem_u32(ap));
            #pragma unroll
            for (int nt = 0; nt < 4; nt++) {
                uint32_t bfr[2];
                int trow = 32 * ln + 8 * nt + (lane & 7);
                int tcol = 128 + ks * 16 + ((lane >> 3) & 1) * 8;
                ldsm_x2(bfr[0], bfr[1], smem_u32(QK + trow * QK_STRIDE + tcol));
                mma_bf16(a2[nt], afr, bfr);
            }
        }
        const float SC = 0.08838834764831845f;  // 128^-0.5
        #pragma unroll
        for (int nt = 0; nt < 4; nt++) {
            int fr = 16 * lm + g;
            int tc = 32 * ln + 8 * nt + 2 * tig;
            LG[fr * LG_STRIDE + tc]           = a2[nt][0] * SC;
            LG[fr * LG_STRIDE + tc + 1]       = a2[nt][1] * SC;
            LG[(fr + 8) * LG_STRIDE + tc]     = a2[nt][2] * SC;
            LG[(fr + 8) * LG_STRIDE + tc + 1] = a2[nt][3] * SC;
        }
    }
    __syncthreads();

    // ---- gather via precomputed table, write ----
    float* outb = out + (size_t)blockIdx.x * 4672;
    #pragma unroll 4
    for (int e = t; e < 4672; e += THREADS) {
        int s = __ldg(&g_tbl[e]);
        float val = NEG_INF;
        if (s >= 0) {
            val = (s & 0x40000000) ? U[s & 0xFFFF] : LG[s];
        }
        outb[e] = val;
    }
}

extern "C" void kernel_launch(void* const* d_in, const int* in_sizes, int n_in,
                              void* d_out, int out_size) {
    const float* x  = (const float*)d_in[0];
    const float* Wq = (const float*)d_in[1];
    const float* bq = (const float*)d_in[2];
    const float* Wk = (const float*)d_in[3];
    const float* bk = (const float*)d_in[4];
    const float* Wu = (const float*)d_in[5];
    const float* bu = (const float*)d_in[6];
    float* out = (float*)d_out;

    const int nrow = in_sizes[0] / KDIM;   // B * 64
    const int grid = nrow / 64;            // 1 board per CTA

    cudaFuncSetAttribute(policy_kernel, cudaFuncAttributeMaxDynamicSharedMemorySize, SMEM_BYTES);

    prep_w<<<1024, 256>>>(Wq, Wk);
    policy_kernel<<<grid, THREADS, SMEM_BYTES>>>(x, bq, bk, Wu, bu, out);
}

// round 17
// speedup vs baseline: 2.2874x; 2.2874x over previous
#include <cuda_runtime.h>
#include <cuda_bf16.h>
#include <cstdint>

#define NEG_INF (-1e9f)
#define KDIM 1024
#define NCOLS 288            // 128 q | 128 k | 9 u | pad -> 288
#define XSTR 72              // X smem stride (bf16 units): 64 + 8 pad
#define WSTR 296             // W smem stride (bf16 units): 288 + 8 pad
#define QK_STRIDE 264
#define LG_STRIDE 68
#define U_STRIDE 12
#define CHUNK 64
#define NCHUNK 16
#define THREADS 256
// mainloop: Xs [2][64][72] bf16 @0 (18432B), Ws [2][64][296] bf16 @18432 (75776B) -> 94208
// epilogue (aliased): QK [64][264] bf16 @0 (33792B), U [64][12] f32 @33792 (3072B),
//                     LG [64][68] f32 @36864 (17408B) -> 54272
// bias (dedicated): @94208, 272 floats -> 1088B
#define BIAS_OFF 94208
#define SMEM_BYTES 95296

__device__ __nv_bfloat16 g_W[KDIM * NCOLS];
__device__ int g_tbl[4672];

__constant__ int c_ddr[8] = {1, 1, 0, -1, -1, -1, 0, 1};
__constant__ int c_ddc[8] = {0, 1, 1, 1, 0, -1, -1, -1};
__constant__ int c_kdr[8] = {2, 1, -1, -2, -2, -1, 1, 2};
__constant__ int c_kdc[8] = {1, 2, 2, 1, -1, -2, -2, -1};

__global__ void prep_w(const float* __restrict__ Wq, const float* __restrict__ Wk,
                       const float* __restrict__ Wu) {
    int k = blockIdx.x;
    int c = threadIdx.x;
    float v;
    if (c < 128)      v = Wq[k * 128 + c];
    else if (c < 256) v = Wk[k * 128 + (c - 128)];
    else if (c < 265) v = Wu[k * 9 + (c - 256)];
    else              v = 0.0f;
    g_W[k * NCOLS + c] = __float2bfloat16(v);

    // fold the gather-table build in: threads 0-4 of each block do 5 entries
    if (c < 5) {
        int e = blockIdx.x * 5 + c;
        if (e < 4672) {
            int f = e / 73, p = e - f * 73;
            int r = f >> 3, cc = f & 7;
            int s = -1;
            if (p < 64) {
                int nr, nc;
                if (p < 56) {
                    int d = p / 7, dist = p - d * 7 + 1;
                    nr = r + c_ddr[d] * dist;
                    nc = cc + c_ddc[d] * dist;
                } else {
                    int i = p - 56;
                    nr = r + c_kdr[i];
                    nc = cc + c_kdc[i];
                }
                if (((unsigned)nr < 8u) && ((unsigned)nc < 8u)) s = f * LG_STRIDE + nr * 8 + nc;
            } else {
                if (r == 6) s = 0x40000000 | (f * U_STRIDE + (p - 64));
            }
            g_tbl[e] = s;
        }
    }
}

// ---------------- device helpers ----------------
__device__ __forceinline__ uint32_t smem_u32(const void* p) {
    return (uint32_t)__cvta_generic_to_shared(p);
}
__device__ __forceinline__ uint32_t pack2(float a, float b) {
    __nv_bfloat162 h = __floats2bfloat162_rn(a, b);
    return *reinterpret_cast<uint32_t*>(&h);
}
__device__ __forceinline__ void ldsm_x4(uint32_t& r0, uint32_t& r1, uint32_t& r2, uint32_t& r3, uint32_t a) {
    asm volatile("ldmatrix.sync.aligned.m8n8.x4.shared.b16 {%0,%1,%2,%3}, [%4];"
                 : "=r"(r0), "=r"(r1), "=r"(r2), "=r"(r3) : "r"(a));
}
__device__ __forceinline__ void ldsm_x4t(uint32_t& r0, uint32_t& r1, uint32_t& r2, uint32_t& r3, uint32_t a) {
    asm volatile("ldmatrix.sync.aligned.m8n8.x4.trans.shared.b16 {%0,%1,%2,%3}, [%4];"
                 : "=r"(r0), "=r"(r1), "=r"(r2), "=r"(r3) : "r"(a));
}
__device__ __forceinline__ void ldsm_x2(uint32_t& r0, uint32_t& r1, uint32_t a) {
    asm volatile("ldmatrix.sync.aligned.m8n8.x2.shared.b16 {%0,%1}, [%2];"
                 : "=r"(r0), "=r"(r1) : "r"(a));
}
__device__ __forceinline__ void ldsm_x2t(uint32_t& r0, uint32_t& r1, uint32_t a) {
    asm volatile("ldmatrix.sync.aligned.m8n8.x2.trans.shared.b16 {%0,%1}, [%2];"
                 : "=r"(r0), "=r"(r1) : "r"(a));
}
__device__ __forceinline__ void mma_bf16(float* d, const uint32_t* a, const uint32_t* b) {
    asm volatile(
        "mma.sync.aligned.m16n8k16.row.col.f32.bf16.bf16.f32 "
        "{%0,%1,%2,%3}, {%4,%5,%6,%7}, {%8,%9}, {%0,%1,%2,%3};"
        : "+f"(d[0]), "+f"(d[1]), "+f"(d[2]), "+f"(d[3])
        : "r"(a[0]), "r"(a[1]), "r"(a[2]), "r"(a[3]), "r"(b[0]), "r"(b[1]));
}
__device__ __forceinline__ void cp_async16(uint32_t dst, const void* src) {
    asm volatile("cp.async.cg.shared.global [%0], [%1], 16;" :: "r"(dst), "l"(src));
}

extern __shared__ char smem[];

__global__ void __launch_bounds__(THREADS, 2)
policy_kernel(const float* __restrict__ x,
              const float* __restrict__ bq, const float* __restrict__ bk,
              const float* __restrict__ bu, float* __restrict__ out) {
    __nv_bfloat16* Xs = (__nv_bfloat16*)smem;            // [2][64][XSTR]
    __nv_bfloat16* Ws = (__nv_bfloat16*)(smem + 18432);  // [2][64][WSTR]
    float* bias_s = (float*)(smem + BIAS_OFF);           // 256 qk | 9 u

    const int t = threadIdx.x;
    const int w = t >> 5, lane = t & 31;
    const int g = lane >> 2, tig = lane & 3;
    const int warp_m = w >> 2, warp_n = w & 3;   // 2x4 warp grid; warp tile 32 x 72

    const float* xbase = x + (size_t)blockIdx.x * 64 * KDIM;  // 1 board

    if (t < 256) bias_s[t] = (t < 128) ? bq[t] : bk[t - 128];
    if (t < 9)   bias_s[256 + t] = bu[t];

    float acc[2][9][4];
    #pragma unroll
    for (int mt = 0; mt < 2; mt++)
        #pragma unroll
        for (int nt = 0; nt < 9; nt++)
            #pragma unroll
            for (int i = 0; i < 4; i++) acc[mt][nt][i] = 0.0f;

    float4 xr[4];

    // 64 rows x 64 cols per chunk: idx = t + i*256 -> row = idx>>3, c8 = idx&7 (8 floats)
    auto load_x = [&](int k0) {
        #pragma unroll
        for (int i = 0; i < 2; i++) {
            int idx = t + i * THREADS;
            int row = idx >> 3, c8 = idx & 7;
            const float* src = xbase + (size_t)row * KDIM + k0 + c8 * 8;
            xr[2 * i]     = *(const float4*)src;
            xr[2 * i + 1] = *(const float4*)(src + 4);
        }
    };
    auto store_x = [&](int buf) {
        __nv_bfloat16* Xb = Xs + buf * 64 * XSTR;
        #pragma unroll
        for (int i = 0; i < 2; i++) {
            int idx = t + i * THREADS;
            int row = idx >> 3, c8 = idx & 7;
            uint4 p;
            p.x = pack2(xr[2 * i].x,     xr[2 * i].y);
            p.y = pack2(xr[2 * i].z,     xr[2 * i].w);
            p.z = pack2(xr[2 * i + 1].x, xr[2 * i + 1].y);
            p.w = pack2(xr[2 * i + 1].z, xr[2 * i + 1].w);
            *(uint4*)(Xb + row * XSTR + c8 * 8) = p;
        }
    };
    auto load_w = [&](int c, int buf) {
        const __nv_bfloat16* src = g_W + (size_t)c * CHUNK * NCOLS;
        __nv_bfloat16* Wb = Ws + buf * 64 * WSTR;
        for (int idx = t; idx < 64 * 36; idx += THREADS) {
            int row = idx / 36, cc = idx - row * 36;
            cp_async16(smem_u32(Wb + row * WSTR + cc * 8), src + row * NCOLS + cc * 8);
        }
        asm volatile("cp.async.commit_group;");
    };
    auto compute = [&](int c) {
        const __nv_bfloat16* Xb = Xs + (c & 1) * 64 * XSTR;
        const __nv_bfloat16* Wb = Ws + (c & 1) * 64 * WSTR;
        const int arow = 32 * warp_m;
        #pragma unroll
        for (int ks = 0; ks < 4; ks++) {
            uint32_t afr[2][4];
            #pragma unroll
            for (int mt = 0; mt < 2; mt++) {
                const __nv_bfloat16* ap =
                    Xb + (arow + 16 * mt + (lane & 15)) * XSTR + ks * 16 + (lane >> 4) * 8;
                ldsm_x4(afr[mt][0], afr[mt][1], afr[mt][2], afr[mt][3], smem_u32(ap));
            }
            const __nv_bfloat16* brow = Wb + (ks * 16 + (lane & 15)) * WSTR + 72 * warp_n;
            #pragma unroll
            for (int nb = 0; nb < 4; nb++) {
                uint32_t bfr[4];
                ldsm_x4t(bfr[0], bfr[1], bfr[2], bfr[3],
                         smem_u32(brow + nb * 16 + (lane >> 4) * 8));
                mma_bf16(acc[0][2 * nb],     afr[0], bfr);
                mma_bf16(acc[1][2 * nb],     afr[1], bfr);
                mma_bf16(acc[0][2 * nb + 1], afr[0], bfr + 2);
                mma_bf16(acc[1][2 * nb + 1], afr[1], bfr + 2);
            }
            {
                uint32_t bfr[2];
                ldsm_x2t(bfr[0], bfr[1], smem_u32(brow + 64));
                mma_bf16(acc[0][8], afr[0], bfr);
                mma_bf16(acc[1][8], afr[1], bfr);
            }
        }
    };

    // ---- mainloop: 16 K-chunks, double buffered (R10-proven schedule) ----
    load_x(0);
    load_w(0, 0);
    store_x(0);
    asm volatile("cp.async.wait_group 0;");
    __syncthreads();
    for (int c = 0; c < NCHUNK; c++) {
        int nb = (c + 1) & 1;
        if (c + 1 < NCHUNK) {
            load_x((c + 1) * CHUNK);
            load_w(c + 1, nb);
        }
        compute(c);
        if (c + 1 < NCHUNK) {
            store_x(nb);
            asm volatile("cp.async.wait_group 0;");
        }
        __syncthreads();
    }

    // ---- epilogue: q,k -> smem bf16 (+bias), u -> smem f32 (+bu) ----
    __nv_bfloat16* QK = (__nv_bfloat16*)smem;   // [64][QK_STRIDE]
    float* U  = (float*)(smem + 33792);         // [64][U_STRIDE]
    float* LG = (float*)(smem + 36864);         // [64][LG_STRIDE]

    #pragma unroll
    for (int mt = 0; mt < 2; mt++) {
        int r0 = 32 * warp_m + 16 * mt + g;
        #pragma unroll
        for (int nt = 0; nt < 9; nt++) {
            int c0 = 72 * warp_n + 8 * nt + 2 * tig;
            #pragma unroll
            for (int half = 0; half < 2; half++) {
                int row = r0 + 8 * half;
                float v0 = acc[mt][nt][2 * half + 0];
                float v1 = acc[mt][nt][2 * half + 1];
                if (c0 < 256) {
                    *(uint32_t*)(QK + row * QK_STRIDE + c0) =
                        pack2(v0 + bias_s[c0], v1 + bias_s[c0 + 1]);
                } else {
                    int uc = c0 - 256;
                    if (uc < 9)     U[row * U_STRIDE + uc]     = v0 + bias_s[256 + uc];
                    if (uc + 1 < 9) U[row * U_STRIDE + uc + 1] = v1 + bias_s[256 + uc + 1];
                }
            }
        }
    }
    __syncthreads();

    // ---- logits = (q @ k^T) * SCALE ----
    {
        const int lm = w & 3, ln = w >> 2;     // 4 m-tiles of 16, 2 n-tiles of 32
        float a2[4][4];
        #pragma unroll
        for (int nt = 0; nt < 4; nt++)
            #pragma unroll
            for (int i = 0; i < 4; i++) a2[nt][i] = 0.0f;

        #pragma unroll
        for (int ks = 0; ks < 8; ks++) {
            uint32_t afr[4];
            const __nv_bfloat16* ap =
                QK + (16 * lm + (lane & 15)) * QK_STRIDE + ks * 16 + (lane >> 4) * 8;
            ldsm_x4(afr[0], afr[1], afr[2], afr[3], smem_u32(ap));
            #pragma unroll
            for (int nt = 0; nt < 4; nt++) {
                uint32_t bfr[2];
                int trow = 32 * ln + 8 * nt + (lane & 7);
                int tcol = 128 + ks * 16 + ((lane >> 3) & 1) * 8;
                ldsm_x2(bfr[0], bfr[1], smem_u32(QK + trow * QK_STRIDE + tcol));
                mma_bf16(a2[nt], afr, bfr);
            }
        }
        const float SC = 0.08838834764831845f;  // 128^-0.5
        #pragma unroll
        for (int nt = 0; nt < 4; nt++) {
            int fr = 16 * lm + g;
            int tc = 32 * ln + 8 * nt + 2 * tig;
            LG[fr * LG_STRIDE + tc]           = a2[nt][0] * SC;
            LG[fr * LG_STRIDE + tc + 1]       = a2[nt][1] * SC;
            LG[(fr + 8) * LG_STRIDE + tc]     = a2[nt][2] * SC;
            LG[(fr + 8) * LG_STRIDE + tc + 1] = a2[nt][3] * SC;
        }
    }
    __syncthreads();

    // ---- gather via precomputed table, write ----
    float* outb = out + (size_t)blockIdx.x * 4672;
    #pragma unroll 4
    for (int e = t; e < 4672; e += THREADS) {
        int s = __ldg(&g_tbl[e]);
        float val = NEG_INF;
        if (s >= 0) {
            val = (s & 0x40000000) ? U[s & 0xFFFF] : LG[s];
        }
        outb[e] = val;
    }
}

extern "C" void kernel_launch(void* const* d_in, const int* in_sizes, int n_in,
                              void* d_out, int out_size) {
    const float* x  = (const float*)d_in[0];
    const float* Wq = (const float*)d_in[1];
    const float* bq = (const float*)d_in[2];
    const float* Wk = (const float*)d_in[3];
    const float* bk = (const float*)d_in[4];
    const float* Wu = (const float*)d_in[5];
    const float* bu = (const float*)d_in[6];
    float* out = (float*)d_out;

    const int nrow = in_sizes[0] / KDIM;   // B * 64
    const int grid = nrow / 64;            // 1 board per CTA

    cudaFuncSetAttribute(policy_kernel, cudaFuncAttributeMaxDynamicSharedMemorySize, SMEM_BYTES);

    prep_w<<<1024, 288>>>(Wq, Wk, Wu);
    policy_kernel<<<grid, THREADS, SMEM_BYTES>>>(x, bq, bk, bu, out);
}